// round 1
// baseline (speedup 1.0000x reference)
#include <cuda_runtime.h>
#include <cstdint>

// ---------------- problem dims ----------------
#define BB   8
#define SS   4096
#define DD   1024
#define HH   16
#define DH   64
#define MTOK (BB*SS)          // 32768 tokens
#define NELEM ((size_t)MTOK*DD)

// ---------------- scratch (device globals; no allocation allowed) ----------------
__device__ float g_xr  [MTOK*DD];     // tf32-rounded x
__device__ float g_wqkv[3*DD*DD];     // tf32-rounded wq,wk,wv (packed)
__device__ float g_wor [DD*DD];       // tf32-rounded wo
__device__ float g_q   [MTOK*DD];
__device__ float g_k   [MTOK*DD];
__device__ float g_v   [MTOK*DD];
__device__ float g_ctx [MTOK*DD];     // tf32-rounded context

// ---------------- tf32 rounding pass ----------------
__device__ __forceinline__ float round_tf32(float x) {
    uint32_t r;
    asm("cvt.rna.tf32.f32 %0, %1;" : "=r"(r) : "f"(x));
    return __uint_as_float(r);
}

__global__ void round_tf32_kernel(float4* __restrict__ dst,
                                  const float4* __restrict__ src, int n4) {
    int i = blockIdx.x * blockDim.x + threadIdx.x;
    if (i < n4) {
        float4 a = src[i];
        a.x = round_tf32(a.x); a.y = round_tf32(a.y);
        a.z = round_tf32(a.z); a.w = round_tf32(a.w);
        dst[i] = a;
    }
}

// ---------------- TF32 GEMM: C[M,N] = A[M,K] @ W[N,K]^T + bias[N] ----------------
// A, W pre-rounded to tf32. 128x128x32 tile, 8 warps (2x4), cp.async 2-stage.
#define BM 128
#define BN 128
#define BK 32
#define LDT 36                      // BK + 4 pad (keeps 16B alignment, kills bank conflicts)
#define STAGE_F (2*BM*LDT)          // floats per stage (A tile + W tile)

__device__ __forceinline__ void cp_async16(uint32_t smem, const void* gmem) {
    asm volatile("cp.async.cg.shared.global [%0], [%1], 16;\n" :: "r"(smem), "l"(gmem));
}

__global__ __launch_bounds__(256, 2)
void gemm_tf32(const float* __restrict__ A, const float* __restrict__ W,
               const float* __restrict__ bias, float* __restrict__ C,
               int M, int N, int K)
{
    extern __shared__ float sm[];
    const int tid  = threadIdx.x;
    const int bm   = blockIdx.y, bn = blockIdx.x;
    const int warp = tid >> 5, lane = tid & 31;
    const int wm   = warp >> 2, wn = warp & 3;     // 2 x 4 warp grid

    const float* Ag = A + (size_t)(bm * BM) * K;
    const float* Wg = W + (size_t)(bn * BN) * K;
    const int NT = K / BK;

    // ---- async stage loader: 128 rows x 8 float4 per tile, 256 threads x 4 f4 each
    auto load_stage = [&](int kt, int s) {
        float* As = sm + s * STAGE_F;
        float* Ws = As + BM * LDT;
        #pragma unroll
        for (int i = 0; i < 4; i++) {
            int e   = tid + i * 256;
            int row = e >> 3;
            int c4  = (e & 7) * 4;
            uint32_t sa = (uint32_t)__cvta_generic_to_shared(&As[row * LDT + c4]);
            cp_async16(sa, Ag + (size_t)row * K + kt * BK + c4);
            uint32_t sw = (uint32_t)__cvta_generic_to_shared(&Ws[row * LDT + c4]);
            cp_async16(sw, Wg + (size_t)row * K + kt * BK + c4);
        }
        asm volatile("cp.async.commit_group;\n");
    };

    load_stage(0, 0);
    load_stage(1, 1);
    asm volatile("cp.async.wait_group 1;\n");
    __syncthreads();

    float acc[4][4][4];
    #pragma unroll
    for (int a = 0; a < 4; a++)
        #pragma unroll
        for (int b = 0; b < 4; b++)
            #pragma unroll
            for (int c = 0; c < 4; c++) acc[a][b][c] = 0.f;

    for (int kt = 0; kt < NT; kt++) {
        const float* As = sm + (kt & 1) * STAGE_F;
        const float* Ws = As + BM * LDT;
        #pragma unroll
        for (int kk = 0; kk < 4; kk++) {
            float af[4][4], bf[4][2];
            const int ar = wm * 64 + (lane >> 2);
            const int ac = kk * 8 + (lane & 3);
            #pragma unroll
            for (int mf = 0; mf < 4; mf++) {
                af[mf][0] = As[(ar + mf * 16    ) * LDT + ac    ];
                af[mf][1] = As[(ar + mf * 16 + 8) * LDT + ac    ];
                af[mf][2] = As[(ar + mf * 16    ) * LDT + ac + 4];
                af[mf][3] = As[(ar + mf * 16 + 8) * LDT + ac + 4];
            }
            const int br = wn * 32 + (lane >> 2);
            #pragma unroll
            for (int nf = 0; nf < 4; nf++) {
                bf[nf][0] = Ws[(br + nf * 8) * LDT + kk * 8 + (lane & 3)    ];
                bf[nf][1] = Ws[(br + nf * 8) * LDT + kk * 8 + (lane & 3) + 4];
            }
            #pragma unroll
            for (int mf = 0; mf < 4; mf++)
                #pragma unroll
                for (int nf = 0; nf < 4; nf++)
                    asm volatile(
                        "mma.sync.aligned.m16n8k8.row.col.f32.tf32.tf32.f32 "
                        "{%0,%1,%2,%3}, {%4,%5,%6,%7}, {%8,%9}, {%0,%1,%2,%3};"
                        : "+f"(acc[mf][nf][0]), "+f"(acc[mf][nf][1]),
                          "+f"(acc[mf][nf][2]), "+f"(acc[mf][nf][3])
                        : "r"(__float_as_uint(af[mf][0])), "r"(__float_as_uint(af[mf][1])),
                          "r"(__float_as_uint(af[mf][2])), "r"(__float_as_uint(af[mf][3])),
                          "r"(__float_as_uint(bf[nf][0])), "r"(__float_as_uint(bf[nf][1])));
        }
        __syncthreads();
        if (kt + 2 < NT) {
            load_stage(kt + 2, kt & 1);
            asm volatile("cp.async.wait_group 1;\n");
        } else {
            asm volatile("cp.async.wait_group 0;\n");
        }
        __syncthreads();
    }

    // ---- epilogue: bias + store (cols 2c,2c+1 contiguous -> float2)
    const int crow0 = bm * BM + wm * 64 + (lane >> 2);
    const int ccol0 = bn * BN + wn * 32 + (lane & 3) * 2;
    #pragma unroll
    for (int mf = 0; mf < 4; mf++) {
        #pragma unroll
        for (int nf = 0; nf < 4; nf++) {
            int r = crow0 + mf * 16;
            int c = ccol0 + nf * 8;
            float b0 = bias[c], b1 = bias[c + 1];
            *(float2*)&C[(size_t)r * N + c] =
                make_float2(acc[mf][nf][0] + b0, acc[mf][nf][1] + b1);
            *(float2*)&C[(size_t)(r + 8) * N + c] =
                make_float2(acc[mf][nf][2] + b0, acc[mf][nf][3] + b1);
        }
    }
}

// ---------------- per-token attention (softmax over HEAD axis) ----------------
// One block (256 threads) per token. scores[h,g] = q[h,:].k[g,:]/8, softmax over g,
// ctx[h,:] = sum_g p[h,g] v[g,:]. Output rounded to tf32 for the O-GEMM.
__global__ void attn_kernel(const float* __restrict__ Q, const float* __restrict__ K,
                            const float* __restrict__ V, float* __restrict__ CTX)
{
    __shared__ float sq[16][68], sk[16][68], sv[16][68], sp[16][17];
    const int t   = blockIdx.x;
    const int tid = threadIdx.x;
    const int h   = tid >> 4;       // 0..15
    const int g   = tid & 15;       // 0..15 (also reused as d4-chunk index)

    const float4* q4 = (const float4*)(Q + (size_t)t * DD);
    const float4* k4 = (const float4*)(K + (size_t)t * DD);
    const float4* v4 = (const float4*)(V + (size_t)t * DD);
    // float4 index tid = h*16 + d4  ->  element h*64 + d4*4
    *(float4*)&sq[h][g * 4] = q4[tid];
    *(float4*)&sk[h][g * 4] = k4[tid];
    *(float4*)&sv[h][g * 4] = v4[tid];
    __syncthreads();

    // scores: thread (h,g)
    float s = 0.f;
    #pragma unroll
    for (int d = 0; d < 16; d++) {
        float4 qa = *(const float4*)&sq[h][d * 4];
        float4 ka = *(const float4*)&sk[g][d * 4];
        s += qa.x * ka.x + qa.y * ka.y + qa.z * ka.z + qa.w * ka.w;
    }
    s *= 0.125f;   // 1/sqrt(64)

    // softmax over g: groups of 16 lanes (aligned within warp)
    float m = s;
    #pragma unroll
    for (int o = 8; o; o >>= 1) m = fmaxf(m, __shfl_xor_sync(0xffffffffu, m, o));
    float e = __expf(s - m);
    float sum = e;
    #pragma unroll
    for (int o = 8; o; o >>= 1) sum += __shfl_xor_sync(0xffffffffu, sum, o);
    sp[h][g] = e / sum;
    __syncthreads();

    // ctx: thread (h, c) computes 4 dims d = c*4..c*4+3
    float4 acc = make_float4(0.f, 0.f, 0.f, 0.f);
    #pragma unroll
    for (int gg = 0; gg < 16; gg++) {
        float p = sp[h][gg];
        float4 va = *(const float4*)&sv[gg][g * 4];
        acc.x += p * va.x; acc.y += p * va.y;
        acc.z += p * va.z; acc.w += p * va.w;
    }
    acc.x = round_tf32(acc.x); acc.y = round_tf32(acc.y);
    acc.z = round_tf32(acc.z); acc.w = round_tf32(acc.w);
    ((float4*)(CTX + (size_t)t * DD))[tid] = acc;
}

// ---------------- launch ----------------
extern "C" void kernel_launch(void* const* d_in, const int* in_sizes, int n_in,
                              void* d_out, int out_size)
{
    const float* x  = (const float*)d_in[0];
    const float* wq = (const float*)d_in[1];
    const float* bq = (const float*)d_in[2];
    const float* wk = (const float*)d_in[3];
    const float* bk = (const float*)d_in[4];
    const float* wv = (const float*)d_in[5];
    const float* bv = (const float*)d_in[6];
    const float* wo = (const float*)d_in[7];
    const float* bo = (const float*)d_in[8];
    float* out = (float*)d_out;

    float *p_xr, *p_wqkv, *p_wor, *p_q, *p_k, *p_v, *p_ctx;
    cudaGetSymbolAddress((void**)&p_xr,   g_xr);
    cudaGetSymbolAddress((void**)&p_wqkv, g_wqkv);
    cudaGetSymbolAddress((void**)&p_wor,  g_wor);
    cudaGetSymbolAddress((void**)&p_q,    g_q);
    cudaGetSymbolAddress((void**)&p_k,    g_k);
    cudaGetSymbolAddress((void**)&p_v,    g_v);
    cudaGetSymbolAddress((void**)&p_ctx,  g_ctx);

    const int smem = STAGE_F * 2 * (int)sizeof(float);   // 73728 B
    cudaFuncSetAttribute(gemm_tf32, cudaFuncAttributeMaxDynamicSharedMemorySize, smem);

    // 1) tf32-round inputs
    {
        int n4 = (int)(NELEM / 4);
        round_tf32_kernel<<<(n4 + 255) / 256, 256>>>((float4*)p_xr, (const float4*)x, n4);
        int w4 = DD * DD / 4;
        round_tf32_kernel<<<(w4 + 255) / 256, 256>>>((float4*)(p_wqkv),            (const float4*)wq, w4);
        round_tf32_kernel<<<(w4 + 255) / 256, 256>>>((float4*)(p_wqkv + DD * DD),  (const float4*)wk, w4);
        round_tf32_kernel<<<(w4 + 255) / 256, 256>>>((float4*)(p_wqkv + 2*DD*DD),  (const float4*)wv, w4);
        round_tf32_kernel<<<(w4 + 255) / 256, 256>>>((float4*)p_wor,               (const float4*)wo, w4);
    }

    // 2) QKV projections
    dim3 gg(DD / BN, MTOK / BM);   // (8, 256)
    gemm_tf32<<<gg, 256, smem>>>(p_xr, p_wqkv,             bq, p_q, MTOK, DD, DD);
    gemm_tf32<<<gg, 256, smem>>>(p_xr, p_wqkv + DD * DD,   bk, p_k, MTOK, DD, DD);
    gemm_tf32<<<gg, 256, smem>>>(p_xr, p_wqkv + 2 * DD*DD, bv, p_v, MTOK, DD, DD);

    // 3) per-token head-softmax attention
    attn_kernel<<<MTOK, 256>>>(p_q, p_k, p_v, p_ctx);

    // 4) output projection
    gemm_tf32<<<gg, 256, smem>>>(p_ctx, p_wor, bo, out, MTOK, DD, DD);
}